// round 4
// baseline (speedup 1.0000x reference)
#include <cuda_runtime.h>
#include <math.h>
#include <stdint.h>

// LiquidNNSensorModel: 2-layer CfC RNN, B=256, T=1024, S=8, H=256.
// R4: no clusters. 64 CTAs x 256 thr (8 warps), G=4 batches per CTA, h in SMEM
// [b][k] so fma.rn.f32x2 packs the k axis. Weights fp32 streamed from L2 in
// fused records (4x LDG.128 per (kq,o) in stage B) with unroll-8 batching.

#define NB 256
#define NT 1024
#define NS 8
#define NH 256
#define G  4
#define NCTA (NB / G)    // 64
#define NTHR 256

typedef unsigned long long ull;

// ---- global scratch ----
// stage A weights: per (kq,o): 2 float4 = (gh_w0 quad, bb_w0_h quad)
__device__ float4 g_WA[64 * NH * 2];
// stage B weights: per (kq,o): 4 float4 = (gx_w1 q, bb_w1_x q, gh_w1 q, bb_w1_h q)
__device__ float4 g_WB[64 * NH * 4];
// cell0 x-part: [k2=4][o]: (g_k, g_k+1, b_k, b_k+1)
__device__ float4 g_WX0[4 * NH];
__device__ float  g_bias[6 * NH];
__device__ float  g_dtT[NT * NB];    // [t][b]

// ---------------------------------------------------------------------------
__global__ void prep_dt_kernel(const float* __restrict__ ts) {
    int i = blockIdx.x * blockDim.x + threadIdx.x;
    if (i >= NB * NT) return;
    int b = i / NT, t = i - b * NT;
    float dt = 1.0f;
    if (t > 0) dt = ts[i] - ts[i - 1];
    g_dtT[t * NB + b] = fmaxf(dt, 1e-6f);
}

__global__ void prep_w_kernel(
    const float* __restrict__ bb_w0, const float* __restrict__ bb_b0,
    const float* __restrict__ gx_w0, const float* __restrict__ gx_b0,
    const float* __restrict__ gh_w0, const float* __restrict__ gb0,
    const float* __restrict__ lt0,
    const float* __restrict__ bb_w1, const float* __restrict__ bb_b1,
    const float* __restrict__ gx_w1, const float* __restrict__ gx_b1,
    const float* __restrict__ gh_w1, const float* __restrict__ gb1,
    const float* __restrict__ lt1)
{
    const int kq = blockIdx.x;     // 0..63
    const int o  = threadIdx.x;    // 0..255
    const int k0 = kq * 4;

    { const float* p = gh_w0 + o * NH + k0;
      g_WA[(kq * NH + o) * 2 + 0] = make_float4(p[0], p[1], p[2], p[3]); }
    { const float* p = bb_w0 + o * (NS + NH) + NS + k0;
      g_WA[(kq * NH + o) * 2 + 1] = make_float4(p[0], p[1], p[2], p[3]); }

    { const float* p = gx_w1 + o * NH + k0;
      g_WB[(kq * NH + o) * 4 + 0] = make_float4(p[0], p[1], p[2], p[3]); }
    { const float* p = bb_w1 + o * (2 * NH) + k0;
      g_WB[(kq * NH + o) * 4 + 1] = make_float4(p[0], p[1], p[2], p[3]); }
    { const float* p = gh_w1 + o * NH + k0;
      g_WB[(kq * NH + o) * 4 + 2] = make_float4(p[0], p[1], p[2], p[3]); }
    { const float* p = bb_w1 + o * (2 * NH) + NH + k0;
      g_WB[(kq * NH + o) * 4 + 3] = make_float4(p[0], p[1], p[2], p[3]); }

    if (kq < 4) {
        const int k = 2 * kq;
        g_WX0[kq * NH + o] = make_float4(gx_w0[o * NS + k], gx_w0[o * NS + k + 1],
                                         bb_w0[o * (NS + NH) + k], bb_w0[o * (NS + NH) + k + 1]);
    }
    if (kq == 0) {
        g_bias[0 * NH + o] = gx_b0[o] + gb0[o];
        g_bias[1 * NH + o] = bb_b0[o];
        g_bias[2 * NH + o] = log1pf(expf(lt0[o]));
        g_bias[3 * NH + o] = gx_b1[o] + gb1[o];
        g_bias[4 * NH + o] = bb_b1[o];
        g_bias[5 * NH + o] = log1pf(expf(lt1[o]));
    }
}

// ---------------------------------------------------------------------------
__device__ __forceinline__ void ffma2(ull& acc, ull a, ull b) {
    asm("fma.rn.f32x2 %0, %1, %2, %0;" : "+l"(acc) : "l"(a), "l"(b));
}
__device__ __forceinline__ float hsum2(ull v) {
    float lo, hi;
    asm("mov.b64 {%0,%1}, %2;" : "=f"(lo), "=f"(hi) : "l"(v));
    return lo + hi;
}
__device__ __forceinline__ float fast_tanh(float x) {
    float y; asm("tanh.approx.f32 %0, %1;" : "=f"(y) : "f"(x)); return y;
}
__device__ __forceinline__ float cfc_one(float ag, float af, float sp, float dt, float hold) {
    const float g = __fdividef(1.f, 1.f + __expf(-ag));
    const float f = fast_tanh(af);
    const float d = __expf(-dt * (sp + fabsf(g)));
    return d * hold + (1.f - d) * f;
}

// ---------------------------------------------------------------------------
__global__ void __launch_bounds__(NTHR, 1)
liquid_main_kernel(
    const float* __restrict__ xs,
    const float* __restrict__ ln_g, const float* __restrict__ ln_b,
    const float* __restrict__ lp_w, const float* __restrict__ lp_b,
    const float* __restrict__ r1_w, const float* __restrict__ r1_b,
    const float* __restrict__ r2_w, const float* __restrict__ r2_b,
    float* __restrict__ out)
{
    __shared__ __align__(16) float h0s[2][G][NH];
    __shared__ __align__(16) float h1s[2][G][NH];
    __shared__ __align__(16) float xn_s[G][NS];
    __shared__ float dt_s[G];
    __shared__ float lat_s[G][32];

    const int tid    = threadIdx.x;      // = output neuron o
    const int batch0 = blockIdx.x * G;

    // zero initial hidden states
    #pragma unroll
    for (int b = 0; b < G; b++) { h0s[0][b][tid] = 0.f; h1s[0][b][tid] = 0.f; }

    // per-thread constants
    const float rbg0 = g_bias[0 * NH + tid];
    const float rbf0 = g_bias[1 * NH + tid];
    const float rsp0 = g_bias[2 * NH + tid];
    const float rbg1 = g_bias[3 * NH + tid];
    const float rbf1 = g_bias[4 * NH + tid];
    const float rsp1 = g_bias[5 * NH + tid];
    ull wxg[4], wxb[4];
    #pragma unroll
    for (int k2 = 0; k2 < 4; k2++) {
        const ulonglong2 v = ((const ulonglong2*)g_WX0)[k2 * NH + tid];
        wxg[k2] = v.x; wxb[k2] = v.y;
    }

    // LN params + x/dt prefetch registers (threads 0..3)
    float lng[NS], lnb[NS];
    float4 px0, px1; float pdt = 1.f;
    if (tid < G) {
        #pragma unroll
        for (int k = 0; k < NS; k++) { lng[k] = ln_g[k]; lnb[k] = ln_b[k]; }
        const float4* xp = (const float4*)(xs + (size_t)(batch0 + tid) * NT * NS);
        px0 = xp[0]; px1 = xp[1];
        pdt = g_dtT[0 * NB + batch0 + tid];
    }
    __syncthreads();

    const ulonglong2* WA = (const ulonglong2*)g_WA + tid * 2;   // [kq*512 + j]
    const ulonglong2* WB = (const ulonglong2*)g_WB + tid * 4;   // [kq*1024 + j]

    int cur = 0;
    for (int t = 0; t < NT; t++) {
        const int nxt = cur ^ 1;

        // ---- publish layernormed x + dt ----
        if (tid < G) {
            float x[NS] = {px0.x, px0.y, px0.z, px0.w, px1.x, px1.y, px1.z, px1.w};
            float mu = 0.f;
            #pragma unroll
            for (int k = 0; k < NS; k++) mu += x[k];
            mu *= 0.125f;
            float var = 0.f;
            #pragma unroll
            for (int k = 0; k < NS; k++) { float d = x[k] - mu; var += d * d; }
            var *= 0.125f;
            const float inv = rsqrtf(var + 1e-5f);
            #pragma unroll
            for (int k = 0; k < NS; k++)
                xn_s[tid][k] = (x[k] - mu) * inv * lng[k] + lnb[k];
            dt_s[tid] = pdt;
        }
        __syncthreads();
        if (tid < G) {   // prefetch next step
            const int tt = (t + 1 < NT) ? t + 1 : NT - 1;
            const float4* xp = (const float4*)(xs + ((size_t)(batch0 + tid) * NT + tt) * NS);
            px0 = xp[0]; px1 = xp[1];
            pdt = g_dtT[tt * NB + batch0 + tid];
        }

        // =================== stage A: CfC cell 0 ===================
        ull ag[G], af[G];
        #pragma unroll
        for (int b = 0; b < G; b++) { ag[b] = 0ull; af[b] = 0ull; }
        // x-part (k-pairs)
        #pragma unroll
        for (int k2 = 0; k2 < 4; k2++) {
            #pragma unroll
            for (int b = 0; b < G; b++) {
                const ull xv = ((const ull*)&xn_s[b][0])[k2];
                ffma2(ag[b], wxg[k2], xv);
                ffma2(af[b], wxb[k2], xv);
            }
        }
        // h-part
        #pragma unroll 8
        for (int kq = 0; kq < 64; kq++) {
            const ulonglong2 wg = WA[kq * 512 + 0];
            const ulonglong2 wb = WA[kq * 512 + 1];
            #pragma unroll
            for (int b = 0; b < G; b++) {
                const ulonglong2 h = *(const ulonglong2*)&h0s[cur][b][kq * 4];
                ffma2(ag[b], wg.x, h.x); ffma2(ag[b], wg.y, h.y);
                ffma2(af[b], wb.x, h.x); ffma2(af[b], wb.y, h.y);
            }
        }
        #pragma unroll
        for (int b = 0; b < G; b++) {
            const float hn = cfc_one(hsum2(ag[b]) + rbg0, hsum2(af[b]) + rbf0,
                                     rsp0, dt_s[b], h0s[cur][b][tid]);
            h0s[nxt][b][tid] = hn;
        }
        __syncthreads();

        // =================== stage B: CfC cell 1 ===================
        #pragma unroll
        for (int b = 0; b < G; b++) { ag[b] = 0ull; af[b] = 0ull; }
        #pragma unroll 8
        for (int kq = 0; kq < 64; kq++) {
            const ulonglong2 xg = WB[kq * 1024 + 0];
            const ulonglong2 xb = WB[kq * 1024 + 1];
            const ulonglong2 hg = WB[kq * 1024 + 2];
            const ulonglong2 hb = WB[kq * 1024 + 3];
            #pragma unroll
            for (int b = 0; b < G; b++) {
                const ulonglong2 x = *(const ulonglong2*)&h0s[nxt][b][kq * 4];
                const ulonglong2 u = *(const ulonglong2*)&h1s[cur][b][kq * 4];
                ffma2(ag[b], xg.x, x.x); ffma2(ag[b], xg.y, x.y);
                ffma2(af[b], xb.x, x.x); ffma2(af[b], xb.y, x.y);
                ffma2(ag[b], hg.x, u.x); ffma2(ag[b], hg.y, u.y);
                ffma2(af[b], hb.x, u.x); ffma2(af[b], hb.y, u.y);
            }
        }
        #pragma unroll
        for (int b = 0; b < G; b++) {
            const float hn = cfc_one(hsum2(ag[b]) + rbg1, hsum2(af[b]) + rbf1,
                                     rsp1, dt_s[b], h1s[cur][b][tid]);
            h1s[nxt][b][tid] = hn;
        }
        __syncthreads();
        cur = nxt;
    }

    // =================== head: latent + risk ===================
    if (tid < G * 32) {
        const int b = tid >> 5, l = tid & 31;
        const float* hv   = &h1s[cur][b][0];
        const float* wrow = lp_w + l * NH;
        float acc = lp_b[l];
        for (int k = 0; k < NH; k++) acc = fmaf(hv[k], __ldg(wrow + k), acc);
        const float lat = tanhf(acc);
        lat_s[b][l] = lat;
        out[(size_t)(batch0 + b) * 32 + l] = lat;
    }
    __syncthreads();
    if (tid < G * 32) {
        const int b = tid >> 5, j = tid & 31;
        const float* wrow = r1_w + j * 32;
        float acc = r1_b[j];
        #pragma unroll
        for (int k = 0; k < 32; k++) acc = fmaf(lat_s[b][k], __ldg(wrow + k), acc);
        const float hid = 0.5f * acc * (1.f + erff(acc * 0.70710678118654752f));
        float v = hid * __ldg(r2_w + j);
        #pragma unroll
        for (int off = 16; off; off >>= 1) v += __shfl_xor_sync(0xffffffffu, v, off);
        if (j == 0) {
            const float risk = 1.f / (1.f + __expf(-(v + r2_b[0])));
            out[NB * 32 + batch0 + b] = risk;
        }
    }
}

// ---------------------------------------------------------------------------
extern "C" void kernel_launch(void* const* d_in, const int* in_sizes, int n_in,
                              void* d_out, int out_size) {
    const float* xs    = (const float*)d_in[0];
    const float* ts    = (const float*)d_in[1];
    const float* ln_g  = (const float*)d_in[2];
    const float* ln_b  = (const float*)d_in[3];
    const float* bb_w0 = (const float*)d_in[4];
    const float* bb_b0 = (const float*)d_in[5];
    const float* gx_w0 = (const float*)d_in[6];
    const float* gx_b0 = (const float*)d_in[7];
    const float* gh_w0 = (const float*)d_in[8];
    const float* gb0   = (const float*)d_in[9];
    const float* lt0   = (const float*)d_in[10];
    const float* bb_w1 = (const float*)d_in[11];
    const float* bb_b1 = (const float*)d_in[12];
    const float* gx_w1 = (const float*)d_in[13];
    const float* gx_b1 = (const float*)d_in[14];
    const float* gh_w1 = (const float*)d_in[15];
    const float* gb1   = (const float*)d_in[16];
    const float* lt1   = (const float*)d_in[17];
    const float* lp_w  = (const float*)d_in[18];
    const float* lp_b  = (const float*)d_in[19];
    const float* r1_w  = (const float*)d_in[20];
    const float* r1_b  = (const float*)d_in[21];
    const float* r2_w  = (const float*)d_in[22];
    const float* r2_b  = (const float*)d_in[23];
    float* out = (float*)d_out;

    prep_dt_kernel<<<(NB * NT) / 256, 256>>>(ts);
    prep_w_kernel<<<64, 256>>>(bb_w0, bb_b0, gx_w0, gx_b0, gh_w0, gb0, lt0,
                               bb_w1, bb_b1, gx_w1, gx_b1, gh_w1, gb1, lt1);
    liquid_main_kernel<<<NCTA, NTHR>>>(xs, ln_g, ln_b, lp_w, lp_b,
                                       r1_w, r1_b, r2_w, r2_b, out);
}

// round 5
// speedup vs baseline: 1.1852x; 1.1852x over previous
#include <cuda_runtime.h>
#include <math.h>
#include <stdint.h>

// LiquidNNSensorModel: 2-layer CfC RNN, B=256, T=1024, S=8, H=256.
// R5: 64 CTAs x 512 threads (16 warps). Thread = (output o, stream-half s):
// s=0 accumulates gate stream, s=1 backbone stream, merged via SMEM per stage.
// Weights fp32 streamed from L2 via __ldcg with deep unroll (MLP), h in SMEM
// [b][k] broadcast, fma.rn.f32x2 over the k axis. Preps fused into ONE kernel
// (2 launches/call) so ncu -s 5 captures the main kernel.

#define NB 256
#define NT 1024
#define NS 8
#define NH 256
#define G  4
#define NCTA 64
#define NTHR 512

typedef unsigned long long ull;

// ---- global scratch ----
__device__ float4 g_SA[2 * 64 * NH];        // [s][kq][o] : s=0 gh_w0 quad, s=1 bb_w0_h quad
__device__ float4 g_SB[2 * 64 * NH * 2];    // [s][kq][o][j]: s=0 (gx_w1,gh_w1), s=1 (bb_w1_x,bb_w1_h)
__device__ float2 g_WX0s[2 * 4 * NH];       // [s][k2][o] : cell0 x-part k-pairs
__device__ float  g_bias[6 * NH];           // bg0, bf0, sp0, bg1, bf1, sp1
__device__ float  g_dtT[NT * NB];           // [t][b]

// ---------------------------------------------------------------------------
__global__ void prep_kernel(
    const float* __restrict__ ts,
    const float* __restrict__ bb_w0, const float* __restrict__ bb_b0,
    const float* __restrict__ gx_w0, const float* __restrict__ gx_b0,
    const float* __restrict__ gh_w0, const float* __restrict__ gb0,
    const float* __restrict__ lt0,
    const float* __restrict__ bb_w1, const float* __restrict__ bb_b1,
    const float* __restrict__ gx_w1, const float* __restrict__ gx_b1,
    const float* __restrict__ gh_w1, const float* __restrict__ gb1,
    const float* __restrict__ lt1)
{
    const int tid = threadIdx.x;          // 0..255
    const int i = blockIdx.x * blockDim.x + tid;
    {   // dt part (all 1024 blocks)
        const int b = i >> 10, t = i & (NT - 1);
        float dt = 1.0f;
        if (t > 0) dt = ts[i] - ts[i - 1];
        g_dtT[t * NB + b] = fmaxf(dt, 1e-6f);
    }
    if (blockIdx.x < 64) {                // weight part
        const int kq = blockIdx.x, o = tid;
        const int k0 = kq * 4;
        { const float* p = gh_w0 + o * NH + k0;
          g_SA[(0 * 64 + kq) * NH + o] = make_float4(p[0], p[1], p[2], p[3]); }
        { const float* p = bb_w0 + o * (NS + NH) + NS + k0;
          g_SA[(1 * 64 + kq) * NH + o] = make_float4(p[0], p[1], p[2], p[3]); }
        { const float* p = gx_w1 + o * NH + k0;
          g_SB[((0 * 64 + kq) * NH + o) * 2 + 0] = make_float4(p[0], p[1], p[2], p[3]); }
        { const float* p = gh_w1 + o * NH + k0;
          g_SB[((0 * 64 + kq) * NH + o) * 2 + 1] = make_float4(p[0], p[1], p[2], p[3]); }
        { const float* p = bb_w1 + o * (2 * NH) + k0;
          g_SB[((1 * 64 + kq) * NH + o) * 2 + 0] = make_float4(p[0], p[1], p[2], p[3]); }
        { const float* p = bb_w1 + o * (2 * NH) + NH + k0;
          g_SB[((1 * 64 + kq) * NH + o) * 2 + 1] = make_float4(p[0], p[1], p[2], p[3]); }
        if (kq < 4) {
            const int k = 2 * kq;
            g_WX0s[(0 * 4 + kq) * NH + o] = make_float2(gx_w0[o * NS + k], gx_w0[o * NS + k + 1]);
            g_WX0s[(1 * 4 + kq) * NH + o] = make_float2(bb_w0[o * (NS + NH) + k],
                                                        bb_w0[o * (NS + NH) + k + 1]);
        }
        if (kq == 0) {
            g_bias[0 * NH + o] = gx_b0[o] + gb0[o];
            g_bias[1 * NH + o] = bb_b0[o];
            g_bias[2 * NH + o] = log1pf(expf(lt0[o]));
            g_bias[3 * NH + o] = gx_b1[o] + gb1[o];
            g_bias[4 * NH + o] = bb_b1[o];
            g_bias[5 * NH + o] = log1pf(expf(lt1[o]));
        }
    }
}

// ---------------------------------------------------------------------------
__device__ __forceinline__ void ffma2(ull& acc, ull a, ull b) {
    asm("fma.rn.f32x2 %0, %1, %2, %0;" : "+l"(acc) : "l"(a), "l"(b));
}
__device__ __forceinline__ float hsum2(ull v) {
    float lo, hi;
    asm("mov.b64 {%0,%1}, %2;" : "=f"(lo), "=f"(hi) : "l"(v));
    return lo + hi;
}
__device__ __forceinline__ float fast_tanh(float x) {
    float y; asm("tanh.approx.f32 %0, %1;" : "=f"(y) : "f"(x)); return y;
}
// af already includes its bias
__device__ __forceinline__ float cfc_one(float ag, float af, float sp, float dt, float hold) {
    const float g = __fdividef(1.f, 1.f + __expf(-ag));
    const float f = fast_tanh(af);
    const float d = __expf(-dt * (sp + fabsf(g)));
    return d * hold + (1.f - d) * f;
}

// ---------------------------------------------------------------------------
__global__ void __launch_bounds__(NTHR, 1)
liquid_main_kernel(
    const float* __restrict__ xs,
    const float* __restrict__ ln_g, const float* __restrict__ ln_b,
    const float* __restrict__ lp_w, const float* __restrict__ lp_b,
    const float* __restrict__ r1_w, const float* __restrict__ r1_b,
    const float* __restrict__ r2_w, const float* __restrict__ r2_b,
    float* __restrict__ out)
{
    __shared__ __align__(16) float h0s[2][G][NH];
    __shared__ __align__(16) float h1s[2][G][NH];
    __shared__ __align__(16) float xn_s[G][NS];
    __shared__ float dt_s[G];
    __shared__ float exg[NH][5];          // pitch 5 -> conflict-free
    __shared__ float lat_s[G][32];

    const int tid = threadIdx.x;
    const int o   = tid & 255;            // output neuron
    const int s   = tid >> 8;             // stream half: 0=gate, 1=backbone
    const int batch0 = blockIdx.x * G;

    if (s == 0) {
        #pragma unroll
        for (int b = 0; b < G; b++) { h0s[0][b][o] = 0.f; h1s[0][b][o] = 0.f; }
    }

    // per-thread constants (half-specific)
    float bg0 = 0.f, bf0 = 0.f, sp0 = 0.f, bg1 = 0.f, bf1 = 0.f, sp1 = 0.f;
    if (s == 0) {
        bg0 = g_bias[0 * NH + o]; sp0 = g_bias[2 * NH + o];
        bg1 = g_bias[3 * NH + o]; sp1 = g_bias[5 * NH + o];
    } else {
        bf0 = g_bias[1 * NH + o];
        bf1 = g_bias[4 * NH + o];
    }
    ull wx[4];
    #pragma unroll
    for (int k2 = 0; k2 < 4; k2++) {
        const float2 v = g_WX0s[(s * 4 + k2) * NH + o];
        wx[k2] = *(const ull*)&v;
    }

    // LN params + x/dt prefetch (threads 0..3)
    float lng[NS], lnb[NS];
    float4 px0, px1; float pdt = 1.f;
    if (tid < G) {
        #pragma unroll
        for (int k = 0; k < NS; k++) { lng[k] = ln_g[k]; lnb[k] = ln_b[k]; }
        const float4* xp = (const float4*)(xs + (size_t)(batch0 + tid) * NT * NS);
        px0 = xp[0]; px1 = xp[1];
        pdt = g_dtT[0 * NB + batch0 + tid];
    }
    __syncthreads();

    const float4* WA = g_SA + (size_t)s * 64 * NH + o;         // + kq*NH
    const float4* WB = g_SB + ((size_t)s * 64 * NH + o) * 2;   // + kq*NH*2 (+1)

    int cur = 0;
    for (int t = 0; t < NT; t++) {
        const int nxt = cur ^ 1;

        // ---- publish layernormed x + dt ----
        if (tid < G) {
            float x[NS] = {px0.x, px0.y, px0.z, px0.w, px1.x, px1.y, px1.z, px1.w};
            float mu = 0.f;
            #pragma unroll
            for (int k = 0; k < NS; k++) mu += x[k];
            mu *= 0.125f;
            float var = 0.f;
            #pragma unroll
            for (int k = 0; k < NS; k++) { float d = x[k] - mu; var += d * d; }
            var *= 0.125f;
            const float inv = rsqrtf(var + 1e-5f);
            #pragma unroll
            for (int k = 0; k < NS; k++)
                xn_s[tid][k] = (x[k] - mu) * inv * lng[k] + lnb[k];
            dt_s[tid] = pdt;
        }
        __syncthreads();
        if (tid < G) {   // prefetch next step
            const int tt = (t + 1 < NT) ? t + 1 : NT - 1;
            const float4* xp = (const float4*)(xs + ((size_t)(batch0 + tid) * NT + tt) * NS);
            px0 = xp[0]; px1 = xp[1];
            pdt = g_dtT[tt * NB + batch0 + tid];
        }

        // =================== stage A: CfC cell 0 (partial per half) ===================
        ull a[G];
        #pragma unroll
        for (int b = 0; b < G; b++) a[b] = 0ull;
        #pragma unroll
        for (int k2 = 0; k2 < 4; k2++) {
            #pragma unroll
            for (int b = 0; b < G; b++) {
                const ull xv = ((const ull*)&xn_s[b][0])[k2];
                ffma2(a[b], wx[k2], xv);
            }
        }
        #pragma unroll 16
        for (int kq = 0; kq < 64; kq++) {
            const float4 wf = __ldcg(WA + kq * NH);
            const ulonglong2 w = *(const ulonglong2*)&wf;
            #pragma unroll
            for (int b = 0; b < G; b++) {
                const ulonglong2 h = *(const ulonglong2*)&h0s[cur][b][kq * 4];
                ffma2(a[b], w.x, h.x);
                ffma2(a[b], w.y, h.y);
            }
        }
        if (s) {
            #pragma unroll
            for (int b = 0; b < G; b++) exg[o][b] = hsum2(a[b]) + bf0;
        }
        __syncthreads();
        if (!s) {
            #pragma unroll
            for (int b = 0; b < G; b++) {
                const float hn = cfc_one(hsum2(a[b]) + bg0, exg[o][b],
                                         sp0, dt_s[b], h0s[cur][b][o]);
                h0s[nxt][b][o] = hn;
            }
        }
        __syncthreads();

        // =================== stage B: CfC cell 1 (partial per half) ===================
        #pragma unroll
        for (int b = 0; b < G; b++) a[b] = 0ull;
        #pragma unroll 8
        for (int kq = 0; kq < 64; kq++) {
            const float4 wf0 = __ldcg(WB + kq * (NH * 2));
            const float4 wf1 = __ldcg(WB + kq * (NH * 2) + 1);
            const ulonglong2 w0 = *(const ulonglong2*)&wf0;   // x-stream quad
            const ulonglong2 w1 = *(const ulonglong2*)&wf1;   // h-stream quad
            #pragma unroll
            for (int b = 0; b < G; b++) {
                const ulonglong2 x = *(const ulonglong2*)&h0s[nxt][b][kq * 4];
                const ulonglong2 u = *(const ulonglong2*)&h1s[cur][b][kq * 4];
                ffma2(a[b], w0.x, x.x);
                ffma2(a[b], w0.y, x.y);
                ffma2(a[b], w1.x, u.x);
                ffma2(a[b], w1.y, u.y);
            }
        }
        if (s) {
            #pragma unroll
            for (int b = 0; b < G; b++) exg[o][b] = hsum2(a[b]) + bf1;
        }
        __syncthreads();
        if (!s) {
            #pragma unroll
            for (int b = 0; b < G; b++) {
                const float hn = cfc_one(hsum2(a[b]) + bg1, exg[o][b],
                                         sp1, dt_s[b], h1s[cur][b][o]);
                h1s[nxt][b][o] = hn;
            }
        }
        __syncthreads();
        cur = nxt;
    }

    // =================== head: latent + risk ===================
    if (tid < G * 32) {
        const int b = tid >> 5, l = tid & 31;
        const float* hv   = &h1s[cur][b][0];
        const float* wrow = lp_w + l * NH;
        float acc = lp_b[l];
        for (int k = 0; k < NH; k++) acc = fmaf(hv[k], __ldg(wrow + k), acc);
        const float lat = tanhf(acc);
        lat_s[b][l] = lat;
        out[(size_t)(batch0 + b) * 32 + l] = lat;
    }
    __syncthreads();
    if (tid < G * 32) {
        const int b = tid >> 5, j = tid & 31;
        const float* wrow = r1_w + j * 32;
        float acc = r1_b[j];
        #pragma unroll
        for (int k = 0; k < 32; k++) acc = fmaf(lat_s[b][k], __ldg(wrow + k), acc);
        const float hid = 0.5f * acc * (1.f + erff(acc * 0.70710678118654752f));
        float v = hid * __ldg(r2_w + j);
        #pragma unroll
        for (int off = 16; off; off >>= 1) v += __shfl_xor_sync(0xffffffffu, v, off);
        if (j == 0) {
            const float risk = 1.f / (1.f + __expf(-(v + r2_b[0])));
            out[NB * 32 + batch0 + b] = risk;
        }
    }
}

// ---------------------------------------------------------------------------
extern "C" void kernel_launch(void* const* d_in, const int* in_sizes, int n_in,
                              void* d_out, int out_size) {
    const float* xs    = (const float*)d_in[0];
    const float* ts    = (const float*)d_in[1];
    const float* ln_g  = (const float*)d_in[2];
    const float* ln_b  = (const float*)d_in[3];
    const float* bb_w0 = (const float*)d_in[4];
    const float* bb_b0 = (const float*)d_in[5];
    const float* gx_w0 = (const float*)d_in[6];
    const float* gx_b0 = (const float*)d_in[7];
    const float* gh_w0 = (const float*)d_in[8];
    const float* gb0   = (const float*)d_in[9];
    const float* lt0   = (const float*)d_in[10];
    const float* bb_w1 = (const float*)d_in[11];
    const float* bb_b1 = (const float*)d_in[12];
    const float* gx_w1 = (const float*)d_in[13];
    const float* gx_b1 = (const float*)d_in[14];
    const float* gh_w1 = (const float*)d_in[15];
    const float* gb1   = (const float*)d_in[16];
    const float* lt1   = (const float*)d_in[17];
    const float* lp_w  = (const float*)d_in[18];
    const float* lp_b  = (const float*)d_in[19];
    const float* r1_w  = (const float*)d_in[20];
    const float* r1_b  = (const float*)d_in[21];
    const float* r2_w  = (const float*)d_in[22];
    const float* r2_b  = (const float*)d_in[23];
    float* out = (float*)d_out;

    prep_kernel<<<1024, 256>>>(ts, bb_w0, bb_b0, gx_w0, gx_b0, gh_w0, gb0, lt0,
                               bb_w1, bb_b1, gx_w1, gx_b1, gh_w1, gb1, lt1);
    liquid_main_kernel<<<NCTA, NTHR>>>(xs, ln_g, ln_b, lp_w, lp_b,
                                       r1_w, r1_b, r2_w, r2_b, out);
}

// round 6
// speedup vs baseline: 3.4276x; 2.8920x over previous
#include <cuda_runtime.h>
#include <math.h>
#include <stdint.h>

// LiquidNNSensorModel: 2-layer CfC RNN, B=256, T=1024, S=8, H=256.
// R6: SMEM-resident weights, no clusters. 128 CTAs = 16 groups x 8 ranks.
// Rank owns 32 outputs; recurrent weights in SMEM, cell1-x weights in registers.
// h exchanged through L2 with per-group atomic spin barrier (2/step).
// Thread = (o-lane, k-seg warp); batches packed in fma.rn.f32x2 lanes.

#define NB 256
#define NT 1024
#define NS 8
#define NH 256
#define NG 16        // groups
#define CSZ 8        // CTAs (ranks) per group
#define GB 16        // batches per group
#define NCTA 128
#define NTHR 256

typedef unsigned long long ull;

// ---- global scratch ----
__device__ float4 g_WA0[CSZ * 64 * 32];   // [rank][kq][ol] gh_w0 quads
__device__ float4 g_WA1[CSZ * 64 * 32];   // bb_w0 h-part
__device__ float4 g_WH0[CSZ * 64 * 32];   // gh_w1
__device__ float4 g_WH1[CSZ * 64 * 32];   // bb_w1 h-part
__device__ float4 g_WX1g[CSZ * 64 * 32];  // gx_w1
__device__ float4 g_WX1b[CSZ * 64 * 32];  // bb_w1 x-part
__device__ float2 g_wx0[CSZ * 8 * 32];    // [rank][k][ol] (gx_w0, bb_w0_x)
__device__ float  g_bias[6 * NH];
__device__ float  g_dtT[NT * NB];         // [t][b]
__device__ float  g_h0x[NG * NH * GB];    // exchange: [grp][k][b]
__device__ float  g_h1x[NG * NH * GB];
__device__ unsigned g_bar[NG];

// ---------------------------------------------------------------------------
__global__ void prep_kernel(
    const float* __restrict__ ts,
    const float* __restrict__ bb_w0, const float* __restrict__ gx_w0,
    const float* __restrict__ gx_b0, const float* __restrict__ gh_w0,
    const float* __restrict__ gb0,   const float* __restrict__ lt0,
    const float* __restrict__ bb_w1, const float* __restrict__ gx_w1,
    const float* __restrict__ gx_b1, const float* __restrict__ gh_w1,
    const float* __restrict__ gb1,   const float* __restrict__ lt1,
    const float* __restrict__ bb_b0, const float* __restrict__ bb_b1)
{
    const int tid = threadIdx.x;
    const int i = blockIdx.x * blockDim.x + tid;
    {   // dt transpose
        const int b = i >> 10, t = i & (NT - 1);
        float dt = 1.0f;
        if (t > 0) dt = ts[i] - ts[i - 1];
        g_dtT[t * NB + b] = fmaxf(dt, 1e-6f);
    }
    if (blockIdx.x < 64) {
        const int kq = blockIdx.x, o = tid;
        const int k0 = kq * 4;
        const int rank = o >> 5, ol = o & 31;
        const int idx = (rank * 64 + kq) * 32 + ol;
        { const float* p = gh_w0 + o * NH + k0;
          g_WA0[idx] = make_float4(p[0], p[1], p[2], p[3]); }
        { const float* p = bb_w0 + o * (NS + NH) + NS + k0;
          g_WA1[idx] = make_float4(p[0], p[1], p[2], p[3]); }
        { const float* p = gh_w1 + o * NH + k0;
          g_WH0[idx] = make_float4(p[0], p[1], p[2], p[3]); }
        { const float* p = bb_w1 + o * (2 * NH) + NH + k0;
          g_WH1[idx] = make_float4(p[0], p[1], p[2], p[3]); }
        { const float* p = gx_w1 + o * NH + k0;
          g_WX1g[idx] = make_float4(p[0], p[1], p[2], p[3]); }
        { const float* p = bb_w1 + o * (2 * NH) + k0;
          g_WX1b[idx] = make_float4(p[0], p[1], p[2], p[3]); }
        if (kq < 8)
            g_wx0[(rank * 8 + kq) * 32 + ol] =
                make_float2(gx_w0[o * NS + kq], bb_w0[o * (NS + NH) + kq]);
        if (kq == 0) {
            g_bias[0 * NH + o] = gx_b0[o] + gb0[o];
            g_bias[1 * NH + o] = bb_b0[o];
            g_bias[2 * NH + o] = log1pf(expf(lt0[o]));
            g_bias[3 * NH + o] = gx_b1[o] + gb1[o];
            g_bias[4 * NH + o] = bb_b1[o];
            g_bias[5 * NH + o] = log1pf(expf(lt1[o]));
        }
    }
    if (blockIdx.x == 64 && tid < NG) g_bar[tid] = 0u;   // reset barrier counters
}

// ---------------------------------------------------------------------------
__device__ __forceinline__ void ffma2(ull& acc, ull a, ull b) {
    asm("fma.rn.f32x2 %0, %1, %2, %0;" : "+l"(acc) : "l"(a), "l"(b));
}
__device__ __forceinline__ void add2(ull& a, ull b) {
    asm("add.rn.f32x2 %0, %0, %1;" : "+l"(a) : "l"(b));
}
__device__ __forceinline__ ull splat2(float v) {
    ull r; asm("mov.b64 %0, {%1,%1};" : "=l"(r) : "f"(v)); return r;
}
__device__ __forceinline__ void unpack2(ull v, float& lo, float& hi) {
    asm("mov.b64 {%0,%1}, %2;" : "=f"(lo), "=f"(hi) : "l"(v));
}
__device__ __forceinline__ float fast_tanh(float x) {
    float y; asm("tanh.approx.f32 %0, %1;" : "=f"(y) : "f"(x)); return y;
}
__device__ __forceinline__ float cfc_one(float ag, float af, float sp, float dt, float hold) {
    const float g = __fdividef(1.f, 1.f + __expf(-ag));
    const float f = fast_tanh(af);
    const float d = __expf(-dt * (sp + fabsf(g)));
    return d * hold + (1.f - d) * f;
}
__device__ __forceinline__ unsigned ld_acq(const unsigned* p) {
    unsigned v;
    asm volatile("ld.acquire.gpu.global.u32 %0, [%1];" : "=r"(v) : "l"(p) : "memory");
    return v;
}

// one k-column MAC: splat weights, 8 batch-pair FFMA2 per stream
#define ACCK(WGC, WBC, HBASE, KIDX) do {                                      \
    const ull sg_ = splat2(WGC);                                              \
    const ull sb_ = splat2(WBC);                                              \
    const ulonglong2* hr_ = (const ulonglong2*)((HBASE) + (KIDX) * GB);       \
    const ulonglong2 p0_ = hr_[0], p1_ = hr_[1], p2_ = hr_[2], p3_ = hr_[3];  \
    ffma2(ag[0], sg_, p0_.x); ffma2(af[0], sb_, p0_.x);                       \
    ffma2(ag[1], sg_, p0_.y); ffma2(af[1], sb_, p0_.y);                       \
    ffma2(ag[2], sg_, p1_.x); ffma2(af[2], sb_, p1_.x);                       \
    ffma2(ag[3], sg_, p1_.y); ffma2(af[3], sb_, p1_.y);                       \
    ffma2(ag[4], sg_, p2_.x); ffma2(af[4], sb_, p2_.x);                       \
    ffma2(ag[5], sg_, p2_.y); ffma2(af[5], sb_, p2_.y);                       \
    ffma2(ag[6], sg_, p3_.x); ffma2(af[6], sb_, p3_.x);                       \
    ffma2(ag[7], sg_, p3_.y); ffma2(af[7], sb_, p3_.y);                       \
} while (0)

// SMEM byte offsets
#define OFF_WA0 0
#define OFF_WA1 32768
#define OFF_WH0 65536
#define OFF_WH1 98304
#define OFF_H0  131072        // [256][16] f32 = 16384
#define OFF_H1  147456        // 16384
#define OFF_RED 163840        // [2][8][8][32] ull = 32768
#define OFF_XN  196608        // [8][16] f32 = 512
#define OFF_DT  197120        // 64
#define OFF_LAT 197184        // 256
#define SMEM_BYTES 197504

__global__ void __launch_bounds__(NTHR, 1)
liquid_main_kernel(
    const float* __restrict__ xs,
    const float* __restrict__ ln_g, const float* __restrict__ ln_b,
    const float* __restrict__ lp_w, const float* __restrict__ lp_b,
    const float* __restrict__ r1_w, const float* __restrict__ r1_b,
    const float* __restrict__ r2_w, const float* __restrict__ r2_b,
    float* __restrict__ out)
{
    extern __shared__ char smem[];
    const float4* WA0 = (const float4*)(smem + OFF_WA0);
    const float4* WA1 = (const float4*)(smem + OFF_WA1);
    const float4* WH0 = (const float4*)(smem + OFF_WH0);
    const float4* WH1 = (const float4*)(smem + OFF_WH1);
    float* h0s  = (float*)(smem + OFF_H0);    // [k][b]
    float* h1s  = (float*)(smem + OFF_H1);
    ull*   red  = (ull*)(smem + OFF_RED);     // [str][bp][ws][ol]
    float* xn_s = (float*)(smem + OFF_XN);    // [k][b]
    float* dt_s = (float*)(smem + OFF_DT);
    float* lat_s = (float*)(smem + OFF_LAT);

    const int tid  = threadIdx.x;
    const int ol   = tid & 31;     // compute role: owned output lane; epi role: output
    const int ws   = tid >> 5;     // compute role: k-segment; epi role: batch-pair
    const int rank = blockIdx.x & 7;
    const int grp  = blockIdx.x >> 3;
    const int og   = rank * 32 + ol;
    const int batch0 = grp * GB;

    // ---- load resident weight slices into SMEM (coalesced) ----
    {
        const float4* s0 = g_WA0 + rank * 2048;  float4* d0 = (float4*)(smem + OFF_WA0);
        const float4* s1 = g_WA1 + rank * 2048;  float4* d1 = (float4*)(smem + OFF_WA1);
        const float4* s2 = g_WH0 + rank * 2048;  float4* d2 = (float4*)(smem + OFF_WH0);
        const float4* s3 = g_WH1 + rank * 2048;  float4* d3 = (float4*)(smem + OFF_WH1);
        for (int i = tid; i < 2048; i += NTHR) {
            d0[i] = s0[i]; d1[i] = s1[i]; d2[i] = s2[i]; d3[i] = s3[i];
        }
    }
    // zero h buffers
    {
        float4* z0 = (float4*)h0s; float4* z1 = (float4*)h1s;
        const float4 zz = make_float4(0.f, 0.f, 0.f, 0.f);
        for (int i = tid; i < 1024; i += NTHR) { z0[i] = zz; z1[i] = zz; }
    }

    // ---- persistent register weights: cell1 x-part (this thread's 8 kq) ----
    float4 wx1g_q[8], wx1b_q[8];
    #pragma unroll
    for (int j = 0; j < 8; j++) {
        wx1g_q[j] = g_WX1g[(rank * 64 + ws * 8 + j) * 32 + ol];
        wx1b_q[j] = g_WX1b[(rank * 64 + ws * 8 + j) * 32 + ol];
    }
    // cell0 x-part (k = ws only), pre-splatted
    ull wx0g2, wx0b2;
    {
        const float2 w = g_wx0[(rank * 8 + ws) * 32 + ol];
        wx0g2 = splat2(w.x); wx0b2 = splat2(w.y);
    }
    // biases for epilogue role (o = ol, same index)
    const float bg0 = g_bias[0 * NH + og];
    const float bf0 = g_bias[1 * NH + og];
    const float sp0 = g_bias[2 * NH + og];
    const float bg1 = g_bias[3 * NH + og];
    const float bf1 = g_bias[4 * NH + og];
    const float sp1 = g_bias[5 * NH + og];

    // LN params + x/dt prefetch (threads 0..15 = batches)
    float lng[NS], lnb[NS];
    float4 px0, px1; float pdt = 1.f;
    if (tid < GB) {
        #pragma unroll
        for (int k = 0; k < NS; k++) { lng[k] = ln_g[k]; lnb[k] = ln_b[k]; }
        const float4* xp = (const float4*)(xs + (size_t)(batch0 + tid) * NT * NS);
        px0 = xp[0]; px1 = xp[1];
        pdt = g_dtT[0 * NB + batch0 + tid];
    }
    __syncthreads();

    unsigned bar_tgt = 0;    // only meaningful in tid 0

    for (int t = 0; t < NT; t++) {
        // ---- publish layernormed x + dt ([k][b] layout) ----
        if (tid < GB) {
            float x[NS] = {px0.x, px0.y, px0.z, px0.w, px1.x, px1.y, px1.z, px1.w};
            float mu = 0.f;
            #pragma unroll
            for (int k = 0; k < NS; k++) mu += x[k];
            mu *= 0.125f;
            float var = 0.f;
            #pragma unroll
            for (int k = 0; k < NS; k++) { float d = x[k] - mu; var += d * d; }
            var *= 0.125f;
            const float inv = rsqrtf(var + 1e-5f);
            #pragma unroll
            for (int k = 0; k < NS; k++)
                xn_s[k * GB + tid] = (x[k] - mu) * inv * lng[k] + lnb[k];
            dt_s[tid] = pdt;
        }
        __syncthreads();
        if (tid < GB) {   // prefetch next step
            const int tt = (t + 1 < NT) ? t + 1 : NT - 1;
            const float4* xp = (const float4*)(xs + ((size_t)(batch0 + tid) * NT + tt) * NS);
            px0 = xp[0]; px1 = xp[1];
            pdt = g_dtT[tt * NB + batch0 + tid];
        }

        // =================== stage A: CfC cell 0 ===================
        ull ag[8], af[8];
        #pragma unroll
        for (int bp = 0; bp < 8; bp++) { ag[bp] = 0ull; af[bp] = 0ull; }
        {   // x-part: this warp handles sensor k = ws
            const ulonglong2* xr = (const ulonglong2*)(xn_s + ws * GB);
            const ulonglong2 q0 = xr[0], q1 = xr[1], q2 = xr[2], q3 = xr[3];
            ffma2(ag[0], wx0g2, q0.x); ffma2(af[0], wx0b2, q0.x);
            ffma2(ag[1], wx0g2, q0.y); ffma2(af[1], wx0b2, q0.y);
            ffma2(ag[2], wx0g2, q1.x); ffma2(af[2], wx0b2, q1.x);
            ffma2(ag[3], wx0g2, q1.y); ffma2(af[3], wx0b2, q1.y);
            ffma2(ag[4], wx0g2, q2.x); ffma2(af[4], wx0b2, q2.x);
            ffma2(ag[5], wx0g2, q2.y); ffma2(af[5], wx0b2, q2.y);
            ffma2(ag[6], wx0g2, q3.x); ffma2(af[6], wx0b2, q3.x);
            ffma2(ag[7], wx0g2, q3.y); ffma2(af[7], wx0b2, q3.y);
        }
        #pragma unroll 2
        for (int kq = 0; kq < 8; kq++) {
            const int kqg = ws * 8 + kq;
            const float4 wg4 = WA0[kqg * 32 + ol];
            const float4 wb4 = WA1[kqg * 32 + ol];
            const int k0 = kqg * 4;
            ACCK(wg4.x, wb4.x, h0s, k0 + 0);
            ACCK(wg4.y, wb4.y, h0s, k0 + 1);
            ACCK(wg4.z, wb4.z, h0s, k0 + 2);
            ACCK(wg4.w, wb4.w, h0s, k0 + 3);
        }
        // ---- reduce partials, epilogue, publish ----
        #pragma unroll
        for (int bp = 0; bp < 8; bp++) {
            red[((0 * 8 + bp) * 8 + ws) * 32 + ol] = ag[bp];
            red[((1 * 8 + bp) * 8 + ws) * 32 + ol] = af[bp];
        }
        __syncthreads();
        {
            const int bp = ws;   // epilogue role: (output ol, batch-pair bp)
            ull g2 = red[((0 * 8 + bp) * 8 + 0) * 32 + ol];
            ull f2 = red[((1 * 8 + bp) * 8 + 0) * 32 + ol];
            #pragma unroll
            for (int w2 = 1; w2 < 8; w2++) {
                add2(g2, red[((0 * 8 + bp) * 8 + w2) * 32 + ol]);
                add2(f2, red[((1 * 8 + bp) * 8 + w2) * 32 + ol]);
            }
            float gA, gB, fA, fB, hA, hB;
            unpack2(g2, gA, gB); unpack2(f2, fA, fB);
            const ull holdp = *(const ull*)(h0s + og * GB + 2 * bp);
            unpack2(holdp, hA, hB);
            const float hnA = cfc_one(gA + bg0, fA + bf0, sp0, dt_s[2 * bp + 0], hA);
            const float hnB = cfc_one(gB + bg0, fB + bf0, sp0, dt_s[2 * bp + 1], hB);
            *(float2*)(g_h0x + ((size_t)grp * NH + og) * GB + 2 * bp) = make_float2(hnA, hnB);
        }
        // ---- group barrier + reload h0 ----
        __syncthreads();
        if (tid == 0) {
            bar_tgt += CSZ;
            __threadfence();
            atomicAdd(&g_bar[grp], 1u);
            while (ld_acq(&g_bar[grp]) < bar_tgt) {}
        }
        __syncthreads();
        {
            const float4* src = (const float4*)(g_h0x + (size_t)grp * NH * GB);
            float4* dst = (float4*)h0s;
            #pragma unroll
            for (int j = 0; j < 4; j++) dst[tid + 256 * j] = __ldcg(src + tid + 256 * j);
        }
        __syncthreads();

        // =================== stage B: CfC cell 1 ===================
        #pragma unroll
        for (int bp = 0; bp < 8; bp++) { ag[bp] = 0ull; af[bp] = 0ull; }
        // h-part (SMEM weights, old h1)
        #pragma unroll 2
        for (int kq = 0; kq < 8; kq++) {
            const int kqg = ws * 8 + kq;
            const float4 wg4 = WH0[kqg * 32 + ol];
            const float4 wb4 = WH1[kqg * 32 + ol];
            const int k0 = kqg * 4;
            ACCK(wg4.x, wb4.x, h1s, k0 + 0);
            ACCK(wg4.y, wb4.y, h1s, k0 + 1);
            ACCK(wg4.z, wb4.z, h1s, k0 + 2);
            ACCK(wg4.w, wb4.w, h1s, k0 + 3);
        }
        // x-part (register weights, new h0)
        #pragma unroll
        for (int j = 0; j < 8; j++) {
            const float4 wg4 = wx1g_q[j];
            const float4 wb4 = wx1b_q[j];
            const int k0 = (ws * 8 + j) * 4;
            ACCK(wg4.x, wb4.x, h0s, k0 + 0);
            ACCK(wg4.y, wb4.y, h0s, k0 + 1);
            ACCK(wg4.z, wb4.z, h0s, k0 + 2);
            ACCK(wg4.w, wb4.w, h0s, k0 + 3);
        }
        // ---- reduce, epilogue, publish ----
        #pragma unroll
        for (int bp = 0; bp < 8; bp++) {
            red[((0 * 8 + bp) * 8 + ws) * 32 + ol] = ag[bp];
            red[((1 * 8 + bp) * 8 + ws) * 32 + ol] = af[bp];
        }
        __syncthreads();
        {
            const int bp = ws;
            ull g2 = red[((0 * 8 + bp) * 8 + 0) * 32 + ol];
            ull f2 = red[((1 * 8 + bp) * 8 + 0) * 32 + ol];
            #pragma unroll
            for (int w2 = 1; w2 < 8; w2++) {
                add2(g2, red[((0 * 8 + bp) * 8 + w2) * 32 + ol]);
                add2(f2, red[((1 * 8 + bp) * 8 + w2) * 32 + ol]);
            }
            float gA, gB, fA, fB, hA, hB;
            unpack2(g2, gA, gB); unpack2(f2, fA, fB);
            const ull holdp = *(const ull*)(h1s + og * GB + 2 * bp);
            unpack2(holdp, hA, hB);
            const float hnA = cfc_one(gA + bg1, fA + bf1, sp1, dt_s[2 * bp + 0], hA);
            const float hnB = cfc_one(gB + bg1, fB + bf1, sp1, dt_s[2 * bp + 1], hB);
            *(float2*)(g_h1x + ((size_t)grp * NH + og) * GB + 2 * bp) = make_float2(hnA, hnB);
        }
        __syncthreads();
        if (tid == 0) {
            bar_tgt += CSZ;
            __threadfence();
            atomicAdd(&g_bar[grp], 1u);
            while (ld_acq(&g_bar[grp]) < bar_tgt) {}
        }
        __syncthreads();
        {
            const float4* src = (const float4*)(g_h1x + (size_t)grp * NH * GB);
            float4* dst = (float4*)h1s;
            #pragma unroll
            for (int j = 0; j < 4; j++) dst[tid + 256 * j] = __ldcg(src + tid + 256 * j);
        }
        __syncthreads();
    }

    // =================== head: latent + risk (2 batches per CTA) ===================
    if (tid < 64) {
        const int i = tid >> 5, l = tid & 31;
        const int lb = rank * 2 + i;
        const int gb = batch0 + lb;
        const float* wrow = lp_w + l * NH;
        float acc = lp_b[l];
        for (int k = 0; k < NH; k++) acc = fmaf(h1s[k * GB + lb], __ldg(wrow + k), acc);
        const float latv = tanhf(acc);
        lat_s[i * 32 + l] = latv;
        out[(size_t)gb * 32 + l] = latv;
    }
    __syncthreads();
    if (tid < 64) {
        const int i = tid >> 5, j = tid & 31;
        const int gb = batch0 + rank * 2 + i;
        const float* wrow = r1_w + j * 32;
        float acc = r1_b[j];
        #pragma unroll
        for (int k = 0; k < 32; k++) acc = fmaf(lat_s[i * 32 + k], __ldg(wrow + k), acc);
        const float hid = 0.5f * acc * (1.f + erff(acc * 0.70710678118654752f));
        float v = hid * __ldg(r2_w + j);
        #pragma unroll
        for (int off = 16; off; off >>= 1) v += __shfl_xor_sync(0xffffffffu, v, off);
        if (j == 0) {
            const float risk = 1.f / (1.f + __expf(-(v + r2_b[0])));
            out[NB * 32 + gb] = risk;
        }
    }
}

// ---------------------------------------------------------------------------
extern "C" void kernel_launch(void* const* d_in, const int* in_sizes, int n_in,
                              void* d_out, int out_size) {
    const float* xs    = (const float*)d_in[0];
    const float* ts    = (const float*)d_in[1];
    const float* ln_g  = (const float*)d_in[2];
    const float* ln_b  = (const float*)d_in[3];
    const float* bb_w0 = (const float*)d_in[4];
    const float* bb_b0 = (const float*)d_in[5];
    const float* gx_w0 = (const float*)d_in[6];
    const float* gx_b0 = (const float*)d_in[7];
    const float* gh_w0 = (const float*)d_in[8];
    const float* gb0   = (const float*)d_in[9];
    const float* lt0   = (const float*)d_in[10];
    const float* bb_w1 = (const float*)d_in[11];
    const float* bb_b1 = (const float*)d_in[12];
    const float* gx_w1 = (const float*)d_in[13];
    const float* gx_b1 = (const float*)d_in[14];
    const float* gh_w1 = (const float*)d_in[15];
    const float* gb1   = (const float*)d_in[16];
    const float* lt1   = (const float*)d_in[17];
    const float* lp_w  = (const float*)d_in[18];
    const float* lp_b  = (const float*)d_in[19];
    const float* r1_w  = (const float*)d_in[20];
    const float* r1_b  = (const float*)d_in[21];
    const float* r2_w  = (const float*)d_in[22];
    const float* r2_b  = (const float*)d_in[23];
    float* out = (float*)d_out;

    cudaFuncSetAttribute(liquid_main_kernel,
                         cudaFuncAttributeMaxDynamicSharedMemorySize, SMEM_BYTES);

    prep_kernel<<<1024, 256>>>(ts, bb_w0, gx_w0, gx_b0, gh_w0, gb0, lt0,
                               bb_w1, gx_w1, gx_b1, gh_w1, gb1, lt1,
                               bb_b0, bb_b1);
    liquid_main_kernel<<<NCTA, NTHR, SMEM_BYTES>>>(
        xs, ln_g, ln_b, lp_w, lp_b, r1_w, r1_b, r2_w, r2_b, out);
}

// round 7
// speedup vs baseline: 3.4436x; 1.0047x over previous
#include <cuda_runtime.h>
#include <math.h>
#include <stdint.h>

// LiquidNNSensorModel: 2-layer CfC RNN, B=256, T=1024, S=8, H=256.
// R7: R6 architecture (SMEM-resident weights, 16 groups x 8 ranks, L2 spin
// barrier) with software-pipelined barriers: stage-B h1-part overlaps bar0,
// stage-A overlaps bar1 of the previous step. Packed ulonglong2 reductions.

#define NB 256
#define NT 1024
#define NS 8
#define NH 256
#define NG 16        // groups
#define CSZ 8        // CTAs (ranks) per group
#define GB 16        // batches per group
#define NCTA 128
#define NTHR 256

typedef unsigned long long ull;

// ---- global scratch ----
__device__ float4 g_WA0[CSZ * 64 * 32];   // [rank][kq][ol] gh_w0 quads
__device__ float4 g_WA1[CSZ * 64 * 32];   // bb_w0 h-part
__device__ float4 g_WH0[CSZ * 64 * 32];   // gh_w1
__device__ float4 g_WH1[CSZ * 64 * 32];   // bb_w1 h-part
__device__ float4 g_WX1g[CSZ * 64 * 32];  // gx_w1
__device__ float4 g_WX1b[CSZ * 64 * 32];  // bb_w1 x-part
__device__ float2 g_wx0[CSZ * 8 * 32];    // [rank][k][ol] (gx_w0, bb_w0_x)
__device__ float  g_bias[6 * NH];
__device__ float  g_dtT[NT * NB];         // [t][b]
__device__ float  g_h0x[NG * NH * GB];    // exchange: [grp][k][b]
__device__ float  g_h1x[NG * NH * GB];
__device__ unsigned g_bar[NG];

// ---------------------------------------------------------------------------
__global__ void prep_kernel(
    const float* __restrict__ ts,
    const float* __restrict__ bb_w0, const float* __restrict__ gx_w0,
    const float* __restrict__ gx_b0, const float* __restrict__ gh_w0,
    const float* __restrict__ gb0,   const float* __restrict__ lt0,
    const float* __restrict__ bb_w1, const float* __restrict__ gx_w1,
    const float* __restrict__ gx_b1, const float* __restrict__ gh_w1,
    const float* __restrict__ gb1,   const float* __restrict__ lt1,
    const float* __restrict__ bb_b0, const float* __restrict__ bb_b1)
{
    const int tid = threadIdx.x;
    const int i = blockIdx.x * blockDim.x + tid;
    {   // dt transpose
        const int b = i >> 10, t = i & (NT - 1);
        float dt = 1.0f;
        if (t > 0) dt = ts[i] - ts[i - 1];
        g_dtT[t * NB + b] = fmaxf(dt, 1e-6f);
    }
    if (i < NG * NH * GB) { g_h0x[i] = 0.f; g_h1x[i] = 0.f; }   // h(-1) = 0
    if (blockIdx.x < 64) {
        const int kq = blockIdx.x, o = tid;
        const int k0 = kq * 4;
        const int rank = o >> 5, ol = o & 31;
        const int idx = (rank * 64 + kq) * 32 + ol;
        { const float* p = gh_w0 + o * NH + k0;
          g_WA0[idx] = make_float4(p[0], p[1], p[2], p[3]); }
        { const float* p = bb_w0 + o * (NS + NH) + NS + k0;
          g_WA1[idx] = make_float4(p[0], p[1], p[2], p[3]); }
        { const float* p = gh_w1 + o * NH + k0;
          g_WH0[idx] = make_float4(p[0], p[1], p[2], p[3]); }
        { const float* p = bb_w1 + o * (2 * NH) + NH + k0;
          g_WH1[idx] = make_float4(p[0], p[1], p[2], p[3]); }
        { const float* p = gx_w1 + o * NH + k0;
          g_WX1g[idx] = make_float4(p[0], p[1], p[2], p[3]); }
        { const float* p = bb_w1 + o * (2 * NH) + k0;
          g_WX1b[idx] = make_float4(p[0], p[1], p[2], p[3]); }
        if (kq < 8)
            g_wx0[(rank * 8 + kq) * 32 + ol] =
                make_float2(gx_w0[o * NS + kq], bb_w0[o * (NS + NH) + kq]);
        if (kq == 0) {
            g_bias[0 * NH + o] = gx_b0[o] + gb0[o];
            g_bias[1 * NH + o] = bb_b0[o];
            g_bias[2 * NH + o] = log1pf(expf(lt0[o]));
            g_bias[3 * NH + o] = gx_b1[o] + gb1[o];
            g_bias[4 * NH + o] = bb_b1[o];
            g_bias[5 * NH + o] = log1pf(expf(lt1[o]));
        }
    }
    if (blockIdx.x == 64 && tid < NG) g_bar[tid] = 0u;
}

// ---------------------------------------------------------------------------
__device__ __forceinline__ void ffma2(ull& acc, ull a, ull b) {
    asm("fma.rn.f32x2 %0, %1, %2, %0;" : "+l"(acc) : "l"(a), "l"(b));
}
__device__ __forceinline__ void add2(ull& a, ull b) {
    asm("add.rn.f32x2 %0, %0, %1;" : "+l"(a) : "l"(b));
}
__device__ __forceinline__ ull splat2(float v) {
    ull r; asm("mov.b64 %0, {%1,%1};" : "=l"(r) : "f"(v)); return r;
}
__device__ __forceinline__ void unpack2(ull v, float& lo, float& hi) {
    asm("mov.b64 {%0,%1}, %2;" : "=f"(lo), "=f"(hi) : "l"(v));
}
__device__ __forceinline__ float fast_tanh(float x) {
    float y; asm("tanh.approx.f32 %0, %1;" : "=f"(y) : "f"(x)); return y;
}
__device__ __forceinline__ float cfc_one(float ag, float af, float sp, float dt, float hold) {
    const float g = __fdividef(1.f, 1.f + __expf(-ag));
    const float f = fast_tanh(af);
    const float d = __expf(-dt * (sp + fabsf(g)));
    return d * hold + (1.f - d) * f;
}
__device__ __forceinline__ unsigned ld_acq(const unsigned* p) {
    unsigned v;
    asm volatile("ld.acquire.gpu.global.u32 %0, [%1];" : "=r"(v) : "l"(p) : "memory");
    return v;
}

// one k-column MAC: splat weights, 8 batch-pair FFMA2 per stream
#define ACCK(WGC, WBC, HBASE, KIDX) do {                                      \
    const ull sg_ = splat2(WGC);                                              \
    const ull sb_ = splat2(WBC);                                              \
    const ulonglong2* hr_ = (const ulonglong2*)((HBASE) + (KIDX) * GB);       \
    const ulonglong2 p0_ = hr_[0], p1_ = hr_[1], p2_ = hr_[2], p3_ = hr_[3];  \
    ffma2(ag[0], sg_, p0_.x); ffma2(af[0], sb_, p0_.x);                       \
    ffma2(ag[1], sg_, p0_.y); ffma2(af[1], sb_, p0_.y);                       \
    ffma2(ag[2], sg_, p1_.x); ffma2(af[2], sb_, p1_.x);                       \
    ffma2(ag[3], sg_, p1_.y); ffma2(af[3], sb_, p1_.y);                       \
    ffma2(ag[4], sg_, p2_.x); ffma2(af[4], sb_, p2_.x);                       \
    ffma2(ag[5], sg_, p2_.y); ffma2(af[5], sb_, p2_.y);                       \
    ffma2(ag[6], sg_, p3_.x); ffma2(af[6], sb_, p3_.x);                       \
    ffma2(ag[7], sg_, p3_.y); ffma2(af[7], sb_, p3_.y);                       \
} while (0)

// SMEM byte offsets
#define OFF_WA0 0
#define OFF_WA1 32768
#define OFF_WH0 65536
#define OFF_WH1 98304
#define OFF_H0  131072        // [256][16] f32 = 16384
#define OFF_H1  147456        // 16384
#define OFF_RED 163840        // [8][8][32] ulonglong2 = 32768
#define OFF_XN  196608        // [8][16] f32 = 512
#define OFF_DT  197120        // 64
#define OFF_LAT 197184        // 256
#define SMEM_BYTES 197504

__global__ void __launch_bounds__(NTHR, 1)
liquid_main_kernel(
    const float* __restrict__ xs,
    const float* __restrict__ ln_g, const float* __restrict__ ln_b,
    const float* __restrict__ lp_w, const float* __restrict__ lp_b,
    const float* __restrict__ r1_w, const float* __restrict__ r1_b,
    const float* __restrict__ r2_w, const float* __restrict__ r2_b,
    float* __restrict__ out)
{
    extern __shared__ char smem[];
    const float4* WA0 = (const float4*)(smem + OFF_WA0);
    const float4* WA1 = (const float4*)(smem + OFF_WA1);
    const float4* WH0 = (const float4*)(smem + OFF_WH0);
    const float4* WH1 = (const float4*)(smem + OFF_WH1);
    float* h0s  = (float*)(smem + OFF_H0);        // [k][b]
    float* h1s  = (float*)(smem + OFF_H1);
    ulonglong2* red = (ulonglong2*)(smem + OFF_RED);   // [bp][ws][ol] (ag, af)
    float* xn_s = (float*)(smem + OFF_XN);        // [k][b]
    float* dt_s = (float*)(smem + OFF_DT);
    float* lat_s = (float*)(smem + OFF_LAT);

    const int tid  = threadIdx.x;
    const int ol   = tid & 31;     // compute: owned output lane / epi: output
    const int ws   = tid >> 5;     // compute: k-segment / epi: batch-pair
    const int rank = blockIdx.x & 7;
    const int grp  = blockIdx.x >> 3;
    const int og   = rank * 32 + ol;
    const int batch0 = grp * GB;

    // ---- load resident weight slices into SMEM (coalesced) ----
    {
        const float4* s0 = g_WA0 + rank * 2048;  float4* d0 = (float4*)(smem + OFF_WA0);
        const float4* s1 = g_WA1 + rank * 2048;  float4* d1 = (float4*)(smem + OFF_WA1);
        const float4* s2 = g_WH0 + rank * 2048;  float4* d2 = (float4*)(smem + OFF_WH0);
        const float4* s3 = g_WH1 + rank * 2048;  float4* d3 = (float4*)(smem + OFF_WH1);
        for (int i = tid; i < 2048; i += NTHR) {
            d0[i] = s0[i]; d1[i] = s1[i]; d2[i] = s2[i]; d3[i] = s3[i];
        }
    }
    // zero h buffers (h(-1) = 0)
    {
        float4* z0 = (float4*)h0s; float4* z1 = (float4*)h1s;
        const float4 zz = make_float4(0.f, 0.f, 0.f, 0.f);
        for (int i = tid; i < 1024; i += NTHR) { z0[i] = zz; z1[i] = zz; }
    }

    // persistent register weights: cell1 x-part (this thread's 8 kq)
    float4 wx1g_q[8], wx1b_q[8];
    #pragma unroll
    for (int j = 0; j < 8; j++) {
        wx1g_q[j] = g_WX1g[(rank * 64 + ws * 8 + j) * 32 + ol];
        wx1b_q[j] = g_WX1b[(rank * 64 + ws * 8 + j) * 32 + ol];
    }
    // cell0 x-part (k = ws only), pre-splatted
    ull wx0g2, wx0b2;
    {
        const float2 w = g_wx0[(rank * 8 + ws) * 32 + ol];
        wx0g2 = splat2(w.x); wx0b2 = splat2(w.y);
    }
    // biases for epilogue role
    const float bg0 = g_bias[0 * NH + og];
    const float bf0 = g_bias[1 * NH + og];
    const float sp0 = g_bias[2 * NH + og];
    const float bg1 = g_bias[3 * NH + og];
    const float bf1 = g_bias[4 * NH + og];
    const float sp1 = g_bias[5 * NH + og];

    // LN params + x/dt prefetch (threads 0..15 = batches)
    float lng[NS], lnb[NS];
    float4 px0, px1; float pdt = 1.f;
    if (tid < GB) {
        #pragma unroll
        for (int k = 0; k < NS; k++) { lng[k] = ln_g[k]; lnb[k] = ln_b[k]; }
        const float4* xp = (const float4*)(xs + (size_t)(batch0 + tid) * NT * NS);
        px0 = xp[0]; px1 = xp[1];
        pdt = g_dtT[0 * NB + batch0 + tid];
    }
    __syncthreads();

    unsigned arr = 0;   // tid0: my arrival count

    for (int t = 0; t < NT; t++) {
        // ---- publish layernormed x + dt ([k][b] layout) ----
        if (tid < GB) {
            float x[NS] = {px0.x, px0.y, px0.z, px0.w, px1.x, px1.y, px1.z, px1.w};
            float mu = 0.f;
            #pragma unroll
            for (int k = 0; k < NS; k++) mu += x[k];
            mu *= 0.125f;
            float var = 0.f;
            #pragma unroll
            for (int k = 0; k < NS; k++) { float d = x[k] - mu; var += d * d; }
            var *= 0.125f;
            const float inv = rsqrtf(var + 1e-5f);
            #pragma unroll
            for (int k = 0; k < NS; k++)
                xn_s[k * GB + tid] = (x[k] - mu) * inv * lng[k] + lnb[k];
            dt_s[tid] = pdt;
        }
        __syncthreads();
        if (tid < GB) {   // prefetch next step
            const int tt = (t + 1 < NT) ? t + 1 : NT - 1;
            const float4* xp = (const float4*)(xs + ((size_t)(batch0 + tid) * NT + tt) * NS);
            px0 = xp[0]; px1 = xp[1];
            pdt = g_dtT[tt * NB + batch0 + tid];
        }

        // =================== stage A: CfC cell 0 (uses h0 = h0(t-1)) ===============
        ull ag[8], af[8];
        #pragma unroll
        for (int bp = 0; bp < 8; bp++) { ag[bp] = 0ull; af[bp] = 0ull; }
        {   // x-part: this warp handles sensor k = ws
            const ulonglong2* xr = (const ulonglong2*)(xn_s + ws * GB);
            const ulonglong2 q0 = xr[0], q1 = xr[1], q2 = xr[2], q3 = xr[3];
            ffma2(ag[0], wx0g2, q0.x); ffma2(af[0], wx0b2, q0.x);
            ffma2(ag[1], wx0g2, q0.y); ffma2(af[1], wx0b2, q0.y);
            ffma2(ag[2], wx0g2, q1.x); ffma2(af[2], wx0b2, q1.x);
            ffma2(ag[3], wx0g2, q1.y); ffma2(af[3], wx0b2, q1.y);
            ffma2(ag[4], wx0g2, q2.x); ffma2(af[4], wx0b2, q2.x);
            ffma2(ag[5], wx0g2, q2.y); ffma2(af[5], wx0b2, q2.y);
            ffma2(ag[6], wx0g2, q3.x); ffma2(af[6], wx0b2, q3.x);
            ffma2(ag[7], wx0g2, q3.y); ffma2(af[7], wx0b2, q3.y);
        }
        #pragma unroll 2
        for (int kq = 0; kq < 8; kq++) {
            const int kqg = ws * 8 + kq;
            const float4 wg4 = WA0[kqg * 32 + ol];
            const float4 wb4 = WA1[kqg * 32 + ol];
            const int k0 = kqg * 4;
            ACCK(wg4.x, wb4.x, h0s, k0 + 0);
            ACCK(wg4.y, wb4.y, h0s, k0 + 1);
            ACCK(wg4.z, wb4.z, h0s, k0 + 2);
            ACCK(wg4.w, wb4.w, h0s, k0 + 3);
        }
        #pragma unroll
        for (int bp = 0; bp < 8; bp++)
            red[(bp * 8 + ws) * 32 + ol] = make_ulonglong2(ag[bp], af[bp]);
        __syncthreads();
        {   // epilogue A: (output ol, batch-pair bp=ws); hold from h0s (still h0(t-1))
            const int bp = ws;
            ull g2 = 0ull, f2 = 0ull;
            #pragma unroll
            for (int w2 = 0; w2 < 8; w2++) {
                const ulonglong2 v = red[(bp * 8 + w2) * 32 + ol];
                add2(g2, v.x); add2(f2, v.y);
            }
            float gA, gB, fA, fB, hA, hB;
            unpack2(g2, gA, gB); unpack2(f2, fA, fB);
            const ull holdp = *(const ull*)(h0s + og * GB + 2 * bp);
            unpack2(holdp, hA, hB);
            const float hnA = cfc_one(gA + bg0, fA + bf0, sp0, dt_s[2 * bp + 0], hA);
            const float hnB = cfc_one(gB + bg0, fB + bf0, sp0, dt_s[2 * bp + 1], hB);
            *(float2*)(g_h0x + ((size_t)grp * NH + og) * GB + 2 * bp) = make_float2(hnA, hnB);
        }
        __syncthreads();
        if (tid == 0) {
            __threadfence();
            atomicAdd(&g_bar[grp], 1u);         // arrive bar0 (phase 2t+1)
            arr++;
            // wait bar1 of previous step (phase 2t) — armed a full stage ago
            const unsigned tgt = 8u * (arr - 1u);
            while (ld_acq(&g_bar[grp]) < tgt) {}
        }
        __syncthreads();
        {   // reload h1s <- h1(t-1)
            const float4* src = (const float4*)(g_h1x + (size_t)grp * NH * GB);
            float4* dst = (float4*)h1s;
            #pragma unroll
            for (int j = 0; j < 4; j++) dst[tid + 256 * j] = __ldcg(src + tid + 256 * j);
        }
        __syncthreads();

        // ============ stage B part 1: h-contribution (old h1) — hides bar0 =========
        #pragma unroll
        for (int bp = 0; bp < 8; bp++) { ag[bp] = 0ull; af[bp] = 0ull; }
        #pragma unroll 2
        for (int kq = 0; kq < 8; kq++) {
            const int kqg = ws * 8 + kq;
            const float4 wg4 = WH0[kqg * 32 + ol];
            const float4 wb4 = WH1[kqg * 32 + ol];
            const int k0 = kqg * 4;
            ACCK(wg4.x, wb4.x, h1s, k0 + 0);
            ACCK(wg4.y, wb4.y, h1s, k0 + 1);
            ACCK(wg4.z, wb4.z, h1s, k0 + 2);
            ACCK(wg4.w, wb4.w, h1s, k0 + 3);
        }
        // ---- wait bar0 (mostly satisfied by now) + reload h0s <- h0(t) ----
        if (tid == 0) {
            const unsigned tgt = 8u * arr;
            while (ld_acq(&g_bar[grp]) < tgt) {}
        }
        __syncthreads();
        {
            const float4* src = (const float4*)(g_h0x + (size_t)grp * NH * GB);
            float4* dst = (float4*)h0s;
            #pragma unroll
            for (int j = 0; j < 4; j++) dst[tid + 256 * j] = __ldcg(src + tid + 256 * j);
        }
        __syncthreads();

        // ============ stage B part 2: x-contribution (new h0, register weights) ====
        #pragma unroll
        for (int j = 0; j < 8; j++) {
            const float4 wg4 = wx1g_q[j];
            const float4 wb4 = wx1b_q[j];
            const int k0 = (ws * 8 + j) * 4;
            ACCK(wg4.x, wb4.x, h0s, k0 + 0);
            ACCK(wg4.y, wb4.y, h0s, k0 + 1);
            ACCK(wg4.z, wb4.z, h0s, k0 + 2);
            ACCK(wg4.w, wb4.w, h0s, k0 + 3);
        }
        #pragma unroll
        for (int bp = 0; bp < 8; bp++)
            red[(bp * 8 + ws) * 32 + ol] = make_ulonglong2(ag[bp], af[bp]);
        __syncthreads();
        {   // epilogue B: hold from h1s (= h1(t-1))
            const int bp = ws;
            ull g2 = 0ull, f2 = 0ull;
            #pragma unroll
            for (int w2 = 0; w2 < 8; w2++) {
                const ulonglong2 v = red[(bp * 8 + w2) * 32 + ol];
                add2(g2, v.x); add2(f2, v.y);
            }
            float gA, gB, fA, fB, hA, hB;
            unpack2(g2, gA, gB); unpack2(f2, fA, fB);
            const ull holdp = *(const ull*)(h1s + og * GB + 2 * bp);
            unpack2(holdp, hA, hB);
            const float hnA = cfc_one(gA + bg1, fA + bf1, sp1, dt_s[2 * bp + 0], hA);
            const float hnB = cfc_one(gB + bg1, fB + bf1, sp1, dt_s[2 * bp + 1], hB);
            *(float2*)(g_h1x + ((size_t)grp * NH + og) * GB + 2 * bp) = make_float2(hnA, hnB);
        }
        __syncthreads();
        if (tid == 0) {
            __threadfence();
            atomicAdd(&g_bar[grp], 1u);         // arrive bar1 (phase 2t+2); wait deferred
            arr++;
        }
        // h0s already holds h0(t) for next stage A; h1s refreshed next iteration.
    }

    // ---- final: wait last bar1, reload h1s = h1(NT-1) for the head ----
    if (tid == 0) {
        const unsigned tgt = 8u * arr;
        while (ld_acq(&g_bar[grp]) < tgt) {}
    }
    __syncthreads();
    {
        const float4* src = (const float4*)(g_h1x + (size_t)grp * NH * GB);
        float4* dst = (float4*)h1s;
        #pragma unroll
        for (int j = 0; j < 4; j++) dst[tid + 256 * j] = __ldcg(src + tid + 256 * j);
    }
    __syncthreads();

    // =================== head: latent + risk (2 batches per CTA) ===================
    if (tid < 64) {
        const int i = tid >> 5, l = tid & 31;
        const int lb = rank * 2 + i;
        const int gb = batch0 + lb;
        const float* wrow = lp_w + l * NH;
        float acc = lp_b[l];
        for (int k = 0; k < NH; k++) acc = fmaf(h1s[k * GB + lb], __ldg(wrow + k), acc);
        const float latv = tanhf(acc);
        lat_s[i * 32 + l] = latv;
        out[(size_t)gb * 32 + l] = latv;
    }
    __syncthreads();
    if (tid < 64) {
        const int i = tid >> 5, j = tid & 31;
        const int gb = batch0 + rank * 2 + i;
        const float* wrow = r1_w + j * 32;
        float acc = r1_b[j];
        #pragma unroll
        for (int k = 0; k < 32; k++) acc = fmaf(lat_s[i * 32 + k], __ldg(wrow + k), acc);
        const float hid = 0.5f * acc * (1.f + erff(acc * 0.70710678118654752f));
        float v = hid * __ldg(r2_w + j);
        #pragma unroll
        for (int off = 16; off; off >>= 1) v += __shfl_xor_sync(0xffffffffu, v, off);
        if (j == 0) {
            const float risk = 1.f / (1.f + __expf(-(v + r2_b[0])));
            out[NB * 32 + gb] = risk;
        }
    }
}

// ---------------------------------------------------------------------------
extern "C" void kernel_launch(void* const* d_in, const int* in_sizes, int n_in,
                              void* d_out, int out_size) {
    const float* xs    = (const float*)d_in[0];
    const float* ts    = (const float*)d_in[1];
    const float* ln_g  = (const float*)d_in[2];
    const float* ln_b  = (const float*)d_in[3];
    const float* bb_w0 = (const float*)d_in[4];
    const float* bb_b0 = (const float*)d_in[5];
    const float* gx_w0 = (const float*)d_in[6];
    const float* gx_b0 = (const float*)d_in[7];
    const float* gh_w0 = (const float*)d_in[8];
    const float* gb0   = (const float*)d_in[9];
    const float* lt0   = (const float*)d_in[10];
    const float* bb_w1 = (const float*)d_in[11];
    const float* bb_b1 = (const float*)d_in[12];
    const float* gx_w1 = (const float*)d_in[13];
    const float* gx_b1 = (const float*)d_in[14];
    const float* gh_w1 = (const float*)d_in[15];
    const float* gb1   = (const float*)d_in[16];
    const float* lt1   = (const float*)d_in[17];
    const float* lp_w  = (const float*)d_in[18];
    const float* lp_b  = (const float*)d_in[19];
    const float* r1_w  = (const float*)d_in[20];
    const float* r1_b  = (const float*)d_in[21];
    const float* r2_w  = (const float*)d_in[22];
    const float* r2_b  = (const float*)d_in[23];
    float* out = (float*)d_out;

    cudaFuncSetAttribute(liquid_main_kernel,
                         cudaFuncAttributeMaxDynamicSharedMemorySize, SMEM_BYTES);

    prep_kernel<<<1024, 256>>>(ts, bb_w0, gx_w0, gx_b0, gh_w0, gb0, lt0,
                               bb_w1, gx_w1, gx_b1, gh_w1, gb1, lt1,
                               bb_b0, bb_b1);
    liquid_main_kernel<<<NCTA, NTHR, SMEM_BYTES>>>(
        xs, ln_g, ln_b, lp_w, lp_b, r1_w, r1_b, r2_w, r2_b, out);
}